// round 17
// baseline (speedup 1.0000x reference)
#include <cuda_runtime.h>
#include <cstdint>

// DiffKS fused, warp-autonomous DUAL-STREAM: FIR (order 6) + order-2 IIR via
// warp affine scan. Each warp owns a span of consecutive 128-sample tiles,
// split into two halves A/B processed interleaved each round (two independent
// dependence graphs per warp -> 2x ILP, no barriers between them).
//   x[t]  = y[t] + sum_{k=1..6} Ae[t,k-1]*y[t-k]
//   out[t]= x[t] - a1[t]*out[t-1] - a2[t]*out[t-2]
// Per stream: private double-buffered cp.async stage (y+Ae, quad pitch 25,
// conflict-free), register-prefetched Al, IIR state chained in registers via
// the w-trick (w_l = I_l(bs); entry = shfl_up(w,1); next bs = shfl(w,31)).
// Row starts reset state exactly; each half-span start runs one 32-sample
// warmup (|a|<=0.25 -> ~0.64/step contraction -> ~6e-7 << 1e-3 gate).

#define BATCH 48
#define TLEN  88200
#define T4    22050
#define Y_F4_ROW  22050
#define AE_F4_ROW 132300
#define AL_F4_ROW 44100
#define YMAX  (Y_F4_ROW - 1)

#define TPB    128
#define TROW   690                   // 32-f4 (128-sample) tiles per row
#define NTILES (BATCH * TROW)        // 33120
#define GRID   444                   // 148 SMs * 3 CTAs
#define NWARPS (GRID * 4)            // 1776 warps; ~18.6 tiles -> ~9.3 per stream
#define FULLM  0xffffffffu

// per stream-stage (float4): y slots 0..33 (halo -2), pad to 36; Ae 8 quads * 25
#define STAGE_F4   236
#define WARP_F4    (4 * STAGE_F4)    // A buf0, A buf1, B buf0, B buf1
#define SMEM_F4    (4 * WARP_F4)     // 3776
#define SMEM_BYTES (SMEM_F4 * 16)    // 60416 -> 3 CTAs/SM

__device__ __forceinline__ void cp16(uint32_t dst, const float4* src) {
    asm volatile("cp.async.ca.shared.global [%0], [%1], 16;" :: "r"(dst), "l"(src));
}
__device__ __forceinline__ void cp16z(uint32_t dst, const float4* src, int sz) {
    asm volatile("cp.async.ca.shared.global [%0], [%1], 16, %2;"
                 :: "r"(dst), "l"(src), "r"(sz));
}
__device__ __forceinline__ void cp_commit() {
    asm volatile("cp.async.commit_group;");
}

__device__ __forceinline__ void map_step(float a1, float a2, float x,
                                         float& m00, float& m01, float& m10,
                                         float& m11, float& v0, float& v1)
{
    float t00 = -(a1*m00 + a2*m10);
    float t01 = -(a1*m01 + a2*m11);
    float tv0 = x - a1*v0 - a2*v1;
    m10 = m00; m11 = m01; v1 = v0;
    m00 = t00; m01 = t01; v0 = tv0;
}

// FIR for one 4-sample group given window (w0,w1,y4) and Ae f4s e0..e5
#define FIR4(x4, w0, w1, y4, e0, e1, e2, e3, e4, e5)                          \
    do {                                                                      \
        float h0 = (w1).w, h1 = (w1).z, h2 = (w1).y, h3 = (w1).x;             \
        float h4 = (w0).w, h5 = (w0).z;                                       \
        (x4).x = (y4).x + (e0).x*h0 + (e0).y*h1 + (e0).z*h2 + (e0).w*h3       \
                        + (e1).x*h4 + (e1).y*h5;                              \
        h5=h4; h4=h3; h3=h2; h2=h1; h1=h0; h0=(y4).x;                         \
        (x4).y = (y4).y + (e1).z*h0 + (e1).w*h1 + (e2).x*h2 + (e2).y*h3       \
                        + (e2).z*h4 + (e2).w*h5;                              \
        h5=h4; h4=h3; h3=h2; h2=h1; h1=h0; h0=(y4).y;                         \
        (x4).z = (y4).z + (e3).x*h0 + (e3).y*h1 + (e3).z*h2 + (e3).w*h3       \
                        + (e4).x*h4 + (e4).y*h5;                              \
        h5=h4; h4=h3; h3=h2; h2=h1; h1=h0; h0=(y4).z;                         \
        (x4).w = (y4).w + (e4).z*h0 + (e4).w*h1 + (e5).x*h2 + (e5).y*h3       \
                        + (e5).z*h4 + (e5).w*h5;                              \
    } while (0)

__global__ void __launch_bounds__(TPB, 3)
diffks_fused(const float* __restrict__ y, const float* __restrict__ Ae,
             const float* __restrict__ Al, float* __restrict__ out)
{
    extern __shared__ float4 sm[];

    const int tid  = threadIdx.x;
    const int lane = tid & 31;
    const int wrp  = tid >> 5;
    const int w    = blockIdx.x * 4 + wrp;

    const int T0 = (int)(((long long)w * NTILES) / NWARPS);
    const int T1 = (int)(((long long)(w + 1) * NTILES) / NWARPS);
    const int Tm = (T0 + T1 + 1) >> 1;            // lenA >= lenB
    const int lenA = Tm - T0, lenB = T1 - Tm;

    float4* smW = sm + wrp * WARP_F4;
    const uint32_t smu = (uint32_t)__cvta_generic_to_shared(smW);

    // ---- stage one tile (y 34 f4 + Ae 192 f4) into slot; one commit ----
    auto stage_issue = [&](int tau, int Tend, int slotF4) {
        tau = min(tau, Tend - 1);
        int br = tau / TROW, tr = tau - br * TROW;
        int G0 = tr * 32;
        const float4* yg  = (const float4*)y  + (size_t)br * Y_F4_ROW;
        const float4* aeg = (const float4*)Ae + (size_t)br * AE_F4_ROW;
        const uint32_t sb = smu + (uint32_t)(slotF4 * 16);
        {
            int gi = G0 - 2 + lane;
            int gc = min(max(gi, 0), YMAX);
            cp16z(sb + (uint32_t)(lane * 16), yg + gc, (gi < 0) ? 0 : 16);
            if (lane < 2) {
                int gi2 = G0 + 30 + lane;          // f = 32+lane
                cp16(sb + (uint32_t)((32 + lane) * 16), yg + min(gi2, YMAX));
            }
        }
        int base = tr * 192;
        #pragma unroll
        for (int j = 0; j < 6; j++) {
            int f = lane + 32 * j;
            int gi = min(base + f, AE_F4_ROW - 1);
            int q = f / 24, k2 = f - 24 * q;
            cp16(sb + (uint32_t)((36 + q * 25 + k2) * 16), aeg + gi);
        }
        cp_commit();
    };

    auto load_al = [&](int tau, int Tend, float4& a0, float4& a1) {
        tau = min(tau, Tend - 1);
        int br = tau / TROW, tr = tau - br * TROW;
        const float4* alg = (const float4*)Al + (size_t)br * AL_F4_ROW;
        int im = min(2 * (tr * 32 + lane), AL_F4_ROW - 2);
        a0 = alg[im]; a1 = alg[im + 1];
    };

    // ---- one-time 32-sample warmup for a mid-row stream start ----
    auto warm = [&](int tau, float& b0, float& b1) {
        int br0 = tau / TROW, tr0 = tau - br0 * TROW;
        b0 = 0.f; b1 = 0.f;
        if (tr0 == 0) return;
        const float4* ygw  = (const float4*)y  + (size_t)br0 * Y_F4_ROW;
        const float4* aegw = (const float4*)Ae + (size_t)br0 * AE_F4_ROW;
        const float4* algw = (const float4*)Al + (size_t)br0 * AL_F4_ROW;
        int W  = tr0 * 32 - 8 + lane;              // lanes 0-7 carry real work
        int Wc = min(W, YMAX);
        float4 yv  = ygw[Wc];
        float4 yv1 = ygw[Wc - 1];
        float4 yv2 = ygw[Wc - 2];
        int ai = min(6 * W, AE_F4_ROW - 6);
        float4 e0 = aegw[ai],     e1 = aegw[ai + 1], e2 = aegw[ai + 2];
        float4 e3 = aegw[ai + 3], e4 = aegw[ai + 4], e5 = aegw[ai + 5];
        int li = min(2 * W, AL_F4_ROW - 2);
        float4 l0 = algw[li], l1 = algw[li + 1];

        float4 x4;
        FIR4(x4, yv2, yv1, yv, e0, e1, e2, e3, e4, e5);

        float m00 = -l0.x, m01 = -l0.y, m10 = 1.f, m11 = 0.f, v0 = x4.x, v1 = 0.f;
        map_step(l0.z, l0.w, x4.y, m00, m01, m10, m11, v0, v1);
        map_step(l1.x, l1.y, x4.z, m00, m01, m10, m11, v0, v1);
        map_step(l1.z, l1.w, x4.w, m00, m01, m10, m11, v0, v1);
        #pragma unroll
        for (int d = 1; d <= 4; d <<= 1) {
            float om00 = __shfl_up_sync(FULLM, m00, d);
            float om01 = __shfl_up_sync(FULLM, m01, d);
            float om10 = __shfl_up_sync(FULLM, m10, d);
            float om11 = __shfl_up_sync(FULLM, m11, d);
            float ov0  = __shfl_up_sync(FULLM, v0,  d);
            float ov1  = __shfl_up_sync(FULLM, v1,  d);
            if (lane >= d) {
                float n00 = m00*om00 + m01*om10;
                float n01 = m00*om01 + m01*om11;
                float n10 = m10*om00 + m11*om10;
                float n11 = m10*om01 + m11*om11;
                float nv0 = m00*ov0 + m01*ov1 + v0;
                float nv1 = m10*ov0 + m11*ov1 + v1;
                m00=n00; m01=n01; m10=n10; m11=n11; v0=nv0; v1=nv1;
            }
        }
        b0 = __shfl_sync(FULLM, v0, 7);
        b1 = __shfl_sync(FULLM, v1, 7);
    };

    // ---- prologue: commits alternate A,B,A,B ----
    stage_issue(T0,     Tm, 0);
    stage_issue(Tm,     T1, 2 * STAGE_F4);
    stage_issue(T0 + 1, Tm, STAGE_F4);
    stage_issue(Tm + 1, T1, 3 * STAGE_F4);

    float4 alcA0, alcA1, alnA0, alnA1, alcB0, alcB1, alnB0, alnB1;
    load_al(T0,     Tm, alcA0, alcA1);
    load_al(Tm,     T1, alcB0, alcB1);
    load_al(T0 + 1, Tm, alnA0, alnA1);
    load_al(Tm + 1, T1, alnB0, alnB1);

    float bsA0, bsA1, bsB0, bsB1;
    warm(T0, bsA0, bsA1);
    warm(Tm, bsB0, bsB1);

    // ---- main loop: one A-tile and one B-tile per round, interleaved ----
    for (int k = 0; k < lenB; k++) {
        asm volatile("cp.async.wait_group 2;");
        __syncwarp();

        const int tA = T0 + k, tB = Tm + k;
        const int brA = tA / TROW, trA = tA - brA * TROW;
        const int brB = tB / TROW, trB = tB - brB * TROW;
        if (trA == 0) { bsA0 = 0.f; bsA1 = 0.f; }
        if (trB == 0) { bsB0 = 0.f; bsB1 = 0.f; }

        const float4* sYA  = smW + (k & 1) * STAGE_F4;
        const float4* sAeA = sYA + 36;
        const float4* sYB  = smW + (2 + (k & 1)) * STAGE_F4;
        const float4* sAeB = sYB + 36;

        // front-load ALL smem reads (buffers reused after the syncwarp below)
        float4 Aw0 = sYA[lane], Aw1 = sYA[lane + 1], Ay4 = sYA[lane + 2];
        const float4* pA = &sAeA[(lane >> 2) * 25 + (lane & 3) * 6];
        float4 Ae0 = pA[0], Ae1 = pA[1], Ae2 = pA[2];
        float4 Ae3 = pA[3], Ae4 = pA[4], Ae5 = pA[5];
        float4 Bw0 = sYB[lane], Bw1 = sYB[lane + 1], By4 = sYB[lane + 2];
        const float4* pB = &sAeB[(lane >> 2) * 25 + (lane & 3) * 6];
        float4 Be0 = pB[0], Be1 = pB[1], Be2 = pB[2];
        float4 Be3 = pB[3], Be4 = pB[4], Be5 = pB[5];
        __syncwarp();

        // refill consumed buffers for tiles k+2 (clamped near span end)
        stage_issue(T0 + k + 2, Tm, (k & 1) * STAGE_F4);
        stage_issue(Tm + k + 2, T1, (2 + (k & 1)) * STAGE_F4);

        const float4 a0A = alcA0, a1A = alcA1, a0B = alcB0, a1B = alcB1;
        alcA0 = alnA0; alcA1 = alnA1; alcB0 = alnB0; alcB1 = alnB1;
        load_al(T0 + k + 2, Tm, alnA0, alnA1);
        load_al(Tm + k + 2, T1, alnB0, alnB1);

        // ---- FIR (independent graphs) ----
        float4 xA, xB;
        FIR4(xA, Aw0, Aw1, Ay4, Ae0, Ae1, Ae2, Ae3, Ae4, Ae5);
        FIR4(xB, Bw0, Bw1, By4, Be0, Be1, Be2, Be3, Be4, Be5);

        // ---- 4-step maps ----
        float Ai00 = -a0A.x, Ai01 = -a0A.y, Ai10 = 1.f, Ai11 = 0.f;
        float Av0 = xA.x, Av1 = 0.f;
        map_step(a0A.z, a0A.w, xA.y, Ai00, Ai01, Ai10, Ai11, Av0, Av1);
        map_step(a1A.x, a1A.y, xA.z, Ai00, Ai01, Ai10, Ai11, Av0, Av1);
        map_step(a1A.z, a1A.w, xA.w, Ai00, Ai01, Ai10, Ai11, Av0, Av1);

        float Bi00 = -a0B.x, Bi01 = -a0B.y, Bi10 = 1.f, Bi11 = 0.f;
        float Bv0 = xB.x, Bv1 = 0.f;
        map_step(a0B.z, a0B.w, xB.y, Bi00, Bi01, Bi10, Bi11, Bv0, Bv1);
        map_step(a1B.x, a1B.y, xB.z, Bi00, Bi01, Bi10, Bi11, Bv0, Bv1);
        map_step(a1B.z, a1B.w, xB.w, Bi00, Bi01, Bi10, Bi11, Bv0, Bv1);

        // ---- interleaved 32-lane inclusive scans ----
        #pragma unroll
        for (int d = 1; d <= 16; d <<= 1) {
            float oa00 = __shfl_up_sync(FULLM, Ai00, d);
            float oa01 = __shfl_up_sync(FULLM, Ai01, d);
            float oa10 = __shfl_up_sync(FULLM, Ai10, d);
            float oa11 = __shfl_up_sync(FULLM, Ai11, d);
            float oav0 = __shfl_up_sync(FULLM, Av0,  d);
            float oav1 = __shfl_up_sync(FULLM, Av1,  d);
            float ob00 = __shfl_up_sync(FULLM, Bi00, d);
            float ob01 = __shfl_up_sync(FULLM, Bi01, d);
            float ob10 = __shfl_up_sync(FULLM, Bi10, d);
            float ob11 = __shfl_up_sync(FULLM, Bi11, d);
            float obv0 = __shfl_up_sync(FULLM, Bv0,  d);
            float obv1 = __shfl_up_sync(FULLM, Bv1,  d);
            if (lane >= d) {
                float n00 = Ai00*oa00 + Ai01*oa10;
                float n01 = Ai00*oa01 + Ai01*oa11;
                float n10 = Ai10*oa00 + Ai11*oa10;
                float n11 = Ai10*oa01 + Ai11*oa11;
                float nv0 = Ai00*oav0 + Ai01*oav1 + Av0;
                float nv1 = Ai10*oav0 + Ai11*oav1 + Av1;
                Ai00=n00; Ai01=n01; Ai10=n10; Ai11=n11; Av0=nv0; Av1=nv1;
                float m00 = Bi00*ob00 + Bi01*ob10;
                float m01 = Bi00*ob01 + Bi01*ob11;
                float m10 = Bi10*ob00 + Bi11*ob10;
                float m11 = Bi10*ob01 + Bi11*ob11;
                float mv0 = Bi00*obv0 + Bi01*obv1 + Bv0;
                float mv1 = Bi10*obv0 + Bi11*obv1 + Bv1;
                Bi00=m00; Bi01=m01; Bi10=m10; Bi11=m11; Bv0=mv0; Bv1=mv1;
            }
        }

        // ---- w-trick + replay + store, both streams ----
        float wA0 = Ai00 * bsA0 + Ai01 * bsA1 + Av0;
        float wA1 = Ai10 * bsA0 + Ai11 * bsA1 + Av1;
        float wB0 = Bi00 * bsB0 + Bi01 * bsB1 + Bv0;
        float wB1 = Bi10 * bsB0 + Bi11 * bsB1 + Bv1;

        float sA1 = __shfl_up_sync(FULLM, wA0, 1);
        float sA2 = __shfl_up_sync(FULLM, wA1, 1);
        float sB1 = __shfl_up_sync(FULLM, wB0, 1);
        float sB2 = __shfl_up_sync(FULLM, wB1, 1);
        if (lane == 0) { sA1 = bsA0; sA2 = bsA1; sB1 = bsB0; sB2 = bsB1; }
        bsA0 = __shfl_sync(FULLM, wA0, 31);
        bsA1 = __shfl_sync(FULLM, wA1, 31);
        bsB0 = __shfl_sync(FULLM, wB0, 31);
        bsB1 = __shfl_sync(FULLM, wB1, 31);

        float4 oA, oB; float yo;
        yo = xA.x - a0A.x*sA1 - a0A.y*sA2;  sA2 = sA1; sA1 = yo; oA.x = yo;
        yo = xA.y - a0A.z*sA1 - a0A.w*sA2;  sA2 = sA1; sA1 = yo; oA.y = yo;
        yo = xA.z - a1A.x*sA1 - a1A.y*sA2;  sA2 = sA1; sA1 = yo; oA.z = yo;
        yo = xA.w - a1A.z*sA1 - a1A.w*sA2;  oA.w = yo;
        yo = xB.x - a0B.x*sB1 - a0B.y*sB2;  sB2 = sB1; sB1 = yo; oB.x = yo;
        yo = xB.y - a0B.z*sB1 - a0B.w*sB2;  sB2 = sB1; sB1 = yo; oB.y = yo;
        yo = xB.z - a1B.x*sB1 - a1B.y*sB2;  sB2 = sB1; sB1 = yo; oB.z = yo;
        yo = xB.w - a1B.z*sB1 - a1B.w*sB2;  oB.w = yo;

        {
            int GA = trA * 32 + lane;
            if (GA < T4)
                reinterpret_cast<float4*>(out + (size_t)brA * TLEN)[GA] = oA;
            int GB = trB * 32 + lane;
            if (GB < T4)
                reinterpret_cast<float4*>(out + (size_t)brB * TLEN)[GB] = oB;
        }
        __syncwarp();
    }

    // ---- epilogue: A has at most one extra tile ----
    asm volatile("cp.async.wait_group 0;");
    __syncwarp();
    if (lenA > lenB) {
        const int k = lenB;
        const int tA = T0 + k;
        const int brA = tA / TROW, trA = tA - brA * TROW;
        if (trA == 0) { bsA0 = 0.f; bsA1 = 0.f; }

        const float4* sYA  = smW + (k & 1) * STAGE_F4;
        const float4* sAeA = sYA + 36;
        float4 Aw0 = sYA[lane], Aw1 = sYA[lane + 1], Ay4 = sYA[lane + 2];
        const float4* pA = &sAeA[(lane >> 2) * 25 + (lane & 3) * 6];
        float4 Ae0 = pA[0], Ae1 = pA[1], Ae2 = pA[2];
        float4 Ae3 = pA[3], Ae4 = pA[4], Ae5 = pA[5];

        const float4 a0A = alcA0, a1A = alcA1;     // holds tile lenB's Al
        float4 xA;
        FIR4(xA, Aw0, Aw1, Ay4, Ae0, Ae1, Ae2, Ae3, Ae4, Ae5);

        float Ai00 = -a0A.x, Ai01 = -a0A.y, Ai10 = 1.f, Ai11 = 0.f;
        float Av0 = xA.x, Av1 = 0.f;
        map_step(a0A.z, a0A.w, xA.y, Ai00, Ai01, Ai10, Ai11, Av0, Av1);
        map_step(a1A.x, a1A.y, xA.z, Ai00, Ai01, Ai10, Ai11, Av0, Av1);
        map_step(a1A.z, a1A.w, xA.w, Ai00, Ai01, Ai10, Ai11, Av0, Av1);

        #pragma unroll
        for (int d = 1; d <= 16; d <<= 1) {
            float oa00 = __shfl_up_sync(FULLM, Ai00, d);
            float oa01 = __shfl_up_sync(FULLM, Ai01, d);
            float oa10 = __shfl_up_sync(FULLM, Ai10, d);
            float oa11 = __shfl_up_sync(FULLM, Ai11, d);
            float oav0 = __shfl_up_sync(FULLM, Av0,  d);
            float oav1 = __shfl_up_sync(FULLM, Av1,  d);
            if (lane >= d) {
                float n00 = Ai00*oa00 + Ai01*oa10;
                float n01 = Ai00*oa01 + Ai01*oa11;
                float n10 = Ai10*oa00 + Ai11*oa10;
                float n11 = Ai10*oa01 + Ai11*oa11;
                float nv0 = Ai00*oav0 + Ai01*oav1 + Av0;
                float nv1 = Ai10*oav0 + Ai11*oav1 + Av1;
                Ai00=n00; Ai01=n01; Ai10=n10; Ai11=n11; Av0=nv0; Av1=nv1;
            }
        }
        float wA0 = Ai00 * bsA0 + Ai01 * bsA1 + Av0;
        float wA1 = Ai10 * bsA0 + Ai11 * bsA1 + Av1;
        float sA1 = __shfl_up_sync(FULLM, wA0, 1);
        float sA2 = __shfl_up_sync(FULLM, wA1, 1);
        if (lane == 0) { sA1 = bsA0; sA2 = bsA1; }

        float4 oA; float yo;
        yo = xA.x - a0A.x*sA1 - a0A.y*sA2;  sA2 = sA1; sA1 = yo; oA.x = yo;
        yo = xA.y - a0A.z*sA1 - a0A.w*sA2;  sA2 = sA1; sA1 = yo; oA.y = yo;
        yo = xA.z - a1A.x*sA1 - a1A.y*sA2;  sA2 = sA1; sA1 = yo; oA.z = yo;
        yo = xA.w - a1A.z*sA1 - a1A.w*sA2;  oA.w = yo;

        int GA = trA * 32 + lane;
        if (GA < T4)
            reinterpret_cast<float4*>(out + (size_t)brA * TLEN)[GA] = oA;
    }
}

extern "C" void kernel_launch(void* const* d_in, const int* in_sizes, int n_in,
                              void* d_out, int out_size)
{
    const float* y  = (const float*)d_in[0];
    const float* Ae = (const float*)d_in[1];
    const float* Al = (const float*)d_in[2];
    float* out = (float*)d_out;

    cudaFuncSetAttribute(diffks_fused,
                         cudaFuncAttributeMaxDynamicSharedMemorySize, SMEM_BYTES);

    diffks_fused<<<GRID, TPB, SMEM_BYTES>>>(y, Ae, Al, out);
}